// round 15
// baseline (speedup 1.0000x reference)
#include <cuda_runtime.h>
#include <cuda_fp16.h>
#include <cstdint>
#include <cstddef>

// ---------------- problem dims ----------------
#define Bx 4
#define Sx 1024
#define Dx 768
#define Hx 12
#define HDx 64
#define FCx 3072
#define Mx (Bx*Sx)            // 4096
#define EPSx 1e-5f
#define INV_SQRT_H 0.28867513459481287f   // 1/sqrt(12)
#define LOG2E 1.4426950408889634f

// ---------------- scratch (static device globals) ----------------
__device__ __half   g_xh  [Mx*Dx];
__device__ __half   g_QKVh[(size_t)3*Mx*Dx];     // Q (pre-scaled, log2 domain) | K | V
__device__ uint32_t g_mpk [(size_t)Mx*32];       // packed mask bits
__device__ __half   g_atth[Mx*Dx];
__device__ float    g_proj2[(size_t)2*Mx*Dx];    // proj split-K partials
__device__ float    g_na  [Mx*Dx];
__device__ __half   g_nah [Mx*Dx];
__device__ __half   g_lin1h[(size_t)Mx*FCx];
__device__ float    g_lin2p[(size_t)4*Mx*Dx];    // FC2 split-K partials
__device__ __half   g_Wqkv[(size_t)Dx*3*Dx];     // [768][2304] row-major K x N
__device__ __half   g_Wfch[Dx*Dx];               // [768][768]
__device__ __half   g_W1h [(size_t)Dx*FCx];      // [768][3072]
__device__ __half   g_W2h [(size_t)FCx*Dx];      // [3072][768]

// ---------------- small helpers ----------------
__device__ __forceinline__ uint32_t smem_to_u32(const void* p) {
    uint32_t a;
    asm("{ .reg .u64 t; cvta.to.shared.u64 t, %1; cvt.u32.u64 %0, t; }" : "=r"(a) : "l"(p));
    return a;
}
__device__ __forceinline__ void cp16(uint32_t dst, const void* src) {
    asm volatile("cp.async.cg.shared.global [%0], [%1], 16;" :: "r"(dst), "l"(src));
}
#define CP_COMMIT() asm volatile("cp.async.commit_group;" ::: "memory")
template<int N> __device__ __forceinline__ void cp_wait() {
    asm volatile("cp.async.wait_group %0;" :: "n"(N) : "memory");
}
__device__ __forceinline__ void ldm_x4(uint32_t& r0, uint32_t& r1, uint32_t& r2, uint32_t& r3,
                                       uint32_t addr) {
    asm volatile("ldmatrix.sync.aligned.m8n8.x4.shared.b16 {%0,%1,%2,%3}, [%4];"
                 : "=r"(r0), "=r"(r1), "=r"(r2), "=r"(r3) : "r"(addr));
}
__device__ __forceinline__ void ldm_x4_t(uint32_t& r0, uint32_t& r1, uint32_t& r2, uint32_t& r3,
                                         uint32_t addr) {
    asm volatile("ldmatrix.sync.aligned.m8n8.x4.trans.shared.b16 {%0,%1,%2,%3}, [%4];"
                 : "=r"(r0), "=r"(r1), "=r"(r2), "=r"(r3) : "r"(addr));
}
__device__ __forceinline__ void mma16816(float* c, const uint32_t* a, uint32_t b0, uint32_t b1) {
    asm volatile(
        "mma.sync.aligned.m16n8k16.row.col.f32.f16.f16.f32 "
        "{%0,%1,%2,%3}, {%4,%5,%6,%7}, {%8,%9}, {%0,%1,%2,%3};"
        : "+f"(c[0]), "+f"(c[1]), "+f"(c[2]), "+f"(c[3])
        : "r"(a[0]), "r"(a[1]), "r"(a[2]), "r"(a[3]), "r"(b0), "r"(b1));
}
__device__ __forceinline__ uint32_t h2u(float a, float b) {
    __half2 h = __floats2half2_rn(a, b);
    return *(uint32_t*)&h;
}

// ---------------- fp16 TC GEMM: C[M,N] = A[M,K] * B[K,N] (B row-major) -----
// k-chunk 64, 3 stages, batched frag loads, early next-chunk issue.
// EPI: 3 fp16+bias+relu | 7 QKV route | 8 split-K partial
static constexpr int STAGES = 3;
static constexpr int PITCHA = 144;                // A: bytes per 64-half row
static constexpr int PITCHB = 272;                // B: bytes per 128-half k-row

template<int NT, int EPI>
__global__ __launch_bounds__(256)
void hgemm(const __half* __restrict__ A, const __half* __restrict__ Bm,
           const void* __restrict__ X, void* __restrict__ C0,
           int Kdim, int lda, int ldb, int ldc)
{
    constexpr int NTILES = NT / 16;
    constexpr int ABYTES = 128 * PITCHA;
    constexpr int BBYTES = 64 * PITCHB;
    constexpr int STB    = ABYTES + BBYTES;

    extern __shared__ __align__(128) char smem[];
    const uint32_t sb = smem_to_u32(smem);

    const int tid   = threadIdx.x;
    const int wid   = tid >> 5;
    const int lane  = tid & 31;
    const int warpM = wid & 3;
    const int warpN = wid >> 2;

    const int m0 = blockIdx.y * 128;
    const int n0 = blockIdx.x * NT;

    if (EPI == 8) {                 // K-slice offset for split-K
        A  += (size_t)blockIdx.z * Kdim;
        Bm += (size_t)blockIdx.z * Kdim * ldb;
    }

    float acc[2][NTILES][4];
    #pragma unroll
    for (int i = 0; i < 2; i++)
        #pragma unroll
        for (int j = 0; j < NTILES; j++)
            #pragma unroll
            for (int k = 0; k < 4; k++) acc[i][j][k] = 0.f;

    const int aRowOff = warpM * 32 + (lane & 7) + ((lane >> 3) & 1) * 8;
    const int aKOff   = (lane >> 4) * 8;
    const int bRow  = (lane & 7) + ((lane >> 3) & 1) * 8;
    const int bColB = ((lane >> 4) & 1) * 16;      // bytes

    const int nch = Kdim >> 6;                     // 64-wide chunks

    auto load_tiles = [&](int c, int s) {
        uint32_t baseA = sb + s * STB;
        uint32_t baseB = baseA + ABYTES;
        int k0 = c * 64;
        #pragma unroll
        for (int i = 0; i < 4; i++) {               // A: 128 rows x 64 halves
            int idx = tid + i * 256;
            int rr = idx >> 3, q = idx & 7;
            cp16(baseA + rr * PITCHA + q * 16,
                 A + (size_t)(m0 + rr) * lda + k0 + q * 8);
        }
        #pragma unroll
        for (int i = 0; i < NT / 32; i++) {         // B: 64 k-rows x NT halves
            int idx = tid + i * 256;
            int rr = idx >> 4, q = idx & 15;
            cp16(baseB + rr * PITCHB + q * 16,
                 Bm + (size_t)(k0 + rr) * ldb + n0 + q * 8);
        }
    };

    #pragma unroll
    for (int c = 0; c < STAGES - 1; c++) { load_tiles(c, c); CP_COMMIT(); }

    for (int c = 0; c < nch; c++) {
        cp_wait<STAGES - 2>();
        __syncthreads();

        // early issue of next chunk into the stage freed at iter c-1
        int cn = c + STAGES - 1;
        if (cn < nch) load_tiles(cn, cn % STAGES);
        CP_COMMIT();

        int s = c % STAGES;
        uint32_t stA = sb + s * STB;
        uint32_t stB = stA + ABYTES;

        #pragma unroll
        for (int ks = 0; ks < 4; ks++) {           // 4 x k16 per chunk
            uint32_t a[2][4];
            #pragma unroll
            for (int mt = 0; mt < 2; mt++)
                ldm_x4(a[mt][0], a[mt][1], a[mt][2], a[mt][3],
                       stA + (aRowOff + mt * 16) * PITCHA + (ks * 16 + aKOff) * 2);
            uint32_t bf[NTILES / 2][4];
            #pragma unroll
            for (int ntp = 0; ntp < NTILES / 2; ntp++)
                ldm_x4_t(bf[ntp][0], bf[ntp][1], bf[ntp][2], bf[ntp][3],
                         stB + (ks * 16 + bRow) * PITCHB
                             + (warpN * (NT / 2) + ntp * 16) * 2 + bColB);
            #pragma unroll
            for (int ntp = 0; ntp < NTILES / 2; ntp++) {
                #pragma unroll
                for (int mt = 0; mt < 2; mt++) {
                    mma16816(acc[mt][ntp * 2 + 0], a[mt], bf[ntp][0], bf[ntp][1]);
                    mma16816(acc[mt][ntp * 2 + 1], a[mt], bf[ntp][2], bf[ntp][3]);
                }
            }
        }
    }

    const int rbase0 = m0 + warpM * 32 + (lane >> 2);
    const int cbase  = n0 + warpN * (NT / 2) + (lane & 3) * 2;

    #pragma unroll
    for (int mt = 0; mt < 2; mt++) {
        #pragma unroll
        for (int nt = 0; nt < NTILES; nt++) {
            int col = cbase + nt * 8;
            #pragma unroll
            for (int hf = 0; hf < 2; hf++) {
                int row = rbase0 + mt * 16 + hf * 8;
                float v0 = acc[mt][nt][hf * 2 + 0];
                float v1 = acc[mt][nt][hf * 2 + 1];
                if (EPI == 8) {
                    float* C = (float*)C0 + (size_t)blockIdx.z * Mx * ldc;
                    *(float2*)&C[(size_t)row * ldc + col] = make_float2(v0, v1);
                } else if (EPI == 7) {
                    __half* C = (__half*)C0;
                    int seg = (col >= 2 * Dx) ? 2 : (col >= Dx ? 1 : 0);
                    int cc  = col - seg * Dx;
                    float scl = (seg == 0) ? (INV_SQRT_H * LOG2E) : 1.f;
                    *(uint32_t*)&C[(size_t)seg * Mx * Dx + (size_t)row * Dx + cc] =
                        h2u(v0 * scl, v1 * scl);
                } else { // EPI == 3
                    const float* bias = (const float*)X;
                    __half* C = (__half*)C0;
                    float o0 = fmaxf(v0 + bias[col], 0.f);
                    float o1 = fmaxf(v1 + bias[col + 1], 0.f);
                    *(uint32_t*)&C[(size_t)row * ldc + col] = h2u(o0, o1);
                }
            }
        }
    }
}

// ---------------- flash attention: fused QK^T/mask/softmax/PV ---------------
// 3-stage K/V ring, early refill issue, single barrier per kv-tile.
static constexpr int FPIT  = 144;    // bytes per 64-half row
static constexpr int QBY   = 128 * FPIT;
static constexpr int TBY   = 64 * FPIT;          // one K or V tile
static constexpr int KVST  = 2 * TBY;            // stage block: K then V
static constexpr int FSMEM = QBY + 3 * KVST;     // 73728

__global__ __launch_bounds__(256, 2)
void flash_kernel(const __half* __restrict__ Qg, const __half* __restrict__ Kg,
                  const __half* __restrict__ Vg, const uint32_t* __restrict__ mpk,
                  __half* __restrict__ Og)
{
    extern __shared__ __align__(128) char smem[];
    const uint32_t sQ  = smem_to_u32(smem);
    const uint32_t sKV = sQ + QBY;

    const int tid = threadIdx.x, wid = tid >> 5, lane = tid & 31;
    const int q0 = blockIdx.x * 128;
    const int z = blockIdx.y, b = z / Hx, h = z - b * Hx;

    const __half* Qp = Qg + ((size_t)b * Sx + q0) * Dx + h * HDx;
    const __half* Kp = Kg + ((size_t)b * Sx) * Dx + h * HDx;
    const __half* Vp = Vg + ((size_t)b * Sx) * Dx + h * HDx;
    const uint32_t* mp = mpk + ((size_t)b * Sx + q0) * 32;

    auto loadKV = [&](int t, int s) {
        const __half* kb = Kp + (size_t)t * 64 * Dx;
        const __half* vb = Vp + (size_t)t * 64 * Dx;
        uint32_t base = sKV + s * KVST;
        #pragma unroll
        for (int i = 0; i < 2; i++) {
            int idx = tid + i * 256;
            int r = idx >> 3, c = idx & 7;
            cp16(base + r * FPIT + c * 16,        kb + (size_t)r * Dx + c * 8);
            cp16(base + TBY + r * FPIT + c * 16,  vb + (size_t)r * Dx + c * 8);
        }
    };

    // prologue: Q rides with chunk-0 group
    #pragma unroll
    for (int i = 0; i < 4; i++) {
        int idx = tid + i * 256;
        int r = idx >> 3, c = idx & 7;
        cp16(sQ + r * FPIT + c * 16, Qp + (size_t)r * Dx + c * 8);
    }
    loadKV(0, 0); CP_COMMIT();
    loadKV(1, 1); CP_COMMIT();

    const int r  = lane >> 2;
    const int cq = lane & 3;
    const int rowL = wid * 16 + r;

    float acc_o[8][4];
    #pragma unroll
    for (int i = 0; i < 8; i++)
        #pragma unroll
        for (int j = 0; j < 4; j++) acc_o[i][j] = 0.f;
    float m0r = -1e30f, m1r = -1e30f, l0 = 0.f, l1 = 0.f;

    const uint32_t qAddrBase = sQ + (wid * 16 + (lane & 15)) * FPIT + (lane >> 4) * 16;
    const int kRow = (lane & 7) + ((lane >> 4) & 1) * 8;
    const int kColB = ((lane >> 3) & 1) * 16;
    const int vRow = (lane & 7) + ((lane >> 3) & 1) * 8;
    const int vColB = ((lane >> 4) & 1) * 16;

    for (int t = 0; t < 16; t++) {
        cp_wait<1>();
        __syncthreads();

        // early refill: stage (t+2)%3 == (t-1)%3, freed at iter t-1
        if (t + 2 < 16) loadKV(t + 2, (t + 2) % 3);
        CP_COMMIT();

        int s = t % 3;
        uint32_t stK = sKV + s * KVST, stV = stK + TBY;

        float sc[8][4];
        #pragma unroll
        for (int i = 0; i < 8; i++)
            #pragma unroll
            for (int j = 0; j < 4; j++) sc[i][j] = 0.f;

        #pragma unroll
        for (int j = 0; j < 4; j++) {
            uint32_t qf[4];
            ldm_x4(qf[0], qf[1], qf[2], qf[3], qAddrBase + j * 32);
            #pragma unroll
            for (int np = 0; np < 4; np++) {
                uint32_t b0, b1, b2, b3;
                ldm_x4(b0, b1, b2, b3,
                       stK + (np * 16 + kRow) * FPIT + j * 32 + kColB);
                mma16816(sc[np * 2 + 0], qf, b0, b1);
                mma16816(sc[np * 2 + 1], qf, b2, b3);
            }
        }

        const uint32_t mw0 = mp[(size_t)rowL * 32 + t * 2];
        const uint32_t mw1 = mp[(size_t)rowL * 32 + t * 2 + 1];
        const uint32_t nw0 = mp[(size_t)(rowL + 8) * 32 + t * 2];
        const uint32_t nw1 = mp[(size_t)(rowL + 8) * 32 + t * 2 + 1];
        #pragma unroll
        for (int nt = 0; nt < 8; nt++) {
            int colb = nt * 8 + 2 * cq;
            uint32_t wr  = (colb < 32) ? mw0 : mw1;
            uint32_t wr8 = (colb < 32) ? nw0 : nw1;
            int sh = colb & 31;
            sc[nt][0] = ((wr  >> sh)       & 1) ? sc[nt][0] : -1e9f;
            sc[nt][1] = ((wr  >> (sh + 1)) & 1) ? sc[nt][1] : -1e9f;
            sc[nt][2] = ((wr8 >> sh)       & 1) ? sc[nt][2] : -1e9f;
            sc[nt][3] = ((wr8 >> (sh + 1)) & 1) ? sc[nt][3] : -1e9f;
        }

        float mx0 = -1e30f, mx1 = -1e30f;
        #pragma unroll
        for (int nt = 0; nt < 8; nt++) {
            mx0 = fmaxf(mx0, fmaxf(sc[nt][0], sc[nt][1]));
            mx1 = fmaxf(mx1, fmaxf(sc[nt][2], sc[nt][3]));
        }
        mx0 = fmaxf(mx0, __shfl_xor_sync(0xffffffffu, mx0, 1));
        mx0 = fmaxf(mx0, __shfl_xor_sync(0xffffffffu, mx0, 2));
        mx1 = fmaxf(mx1, __shfl_xor_sync(0xffffffffu, mx1, 1));
        mx1 = fmaxf(mx1, __shfl_xor_sync(0xffffffffu, mx1, 2));

        float mn0 = fmaxf(m0r, mx0), mn1 = fmaxf(m1r, mx1);
        float f0 = exp2f(m0r - mn0), f1 = exp2f(m1r - mn1);
        m0r = mn0; m1r = mn1;

        float s0 = 0.f, s1 = 0.f;
        #pragma unroll
        for (int nt = 0; nt < 8; nt++) {
            sc[nt][0] = exp2f(sc[nt][0] - mn0);
            sc[nt][1] = exp2f(sc[nt][1] - mn0);
            sc[nt][2] = exp2f(sc[nt][2] - mn1);
            sc[nt][3] = exp2f(sc[nt][3] - mn1);
            s0 += sc[nt][0] + sc[nt][1];
            s1 += sc[nt][2] + sc[nt][3];
        }
        s0 += __shfl_xor_sync(0xffffffffu, s0, 1);
        s0 += __shfl_xor_sync(0xffffffffu, s0, 2);
        s1 += __shfl_xor_sync(0xffffffffu, s1, 1);
        s1 += __shfl_xor_sync(0xffffffffu, s1, 2);
        l0 = l0 * f0 + s0;
        l1 = l1 * f1 + s1;

        #pragma unroll
        for (int nt = 0; nt < 8; nt++) {
            acc_o[nt][0] *= f0; acc_o[nt][1] *= f0;
            acc_o[nt][2] *= f1; acc_o[nt][3] *= f1;
        }

        uint32_t ph[4][4];
        #pragma unroll
        for (int j = 0; j < 4; j++) {
            ph[j][0] = h2u(sc[2*j  ][0], sc[2*j  ][1]);
            ph[j][1] = h2u(sc[2*j  ][2], sc[2*j  ][3]);
            ph[j][2] = h2u(sc[2*j+1][0], sc[2*j+1][1]);
            ph[j][3] = h2u(sc[2*j+1][2], sc[2*j+1][3]);
        }
        #pragma unroll
        for (int j = 0; j < 4; j++) {
            #pragma unroll
            for (int nn = 0; nn < 4; nn++) {
                uint32_t b0, b1, b2, b3;
                ldm_x4_t(b0, b1, b2, b3,
                         stV + (j * 16 + vRow) * FPIT + nn * 32 + vColB);
                mma16816(acc_o[nn * 2 + 0], ph[j], b0, b1);
                mma16816(acc_o[nn * 2 + 1], ph[j], b2, b3);
            }
        }
    }

    float i0 = 1.f / l0, i1 = 1.f / l1;
    __half* Op = Og + ((size_t)b * Sx + q0 + wid * 16) * Dx + h * HDx;
    #pragma unroll
    for (int nt = 0; nt < 8; nt++) {
        int col = nt * 8 + 2 * cq;
        *(uint32_t*)&Op[(size_t)r * Dx + col] =
            h2u(acc_o[nt][0] * i0, acc_o[nt][1] * i0);
        *(uint32_t*)&Op[(size_t)(r + 8) * Dx + col] =
            h2u(acc_o[nt][2] * i1, acc_o[nt][3] * i1);
    }
}

// ---------------- fused fp32->fp16 conversions + mask bit-packing -----------
#define CVT_N0 (Mx*Dx)
#define CVT_N1 (Dx*Dx)
#define CVT_N5 (Dx*FCx)
#define CVT_TOT (CVT_N0 + 4*CVT_N1 + 2*CVT_N5)   // 10,223,616
#define CVT_BLOCKS (CVT_TOT / 4 / 256)           // 9984
#define PK_BLOCKS (Mx / 8)                       // 512

__global__ __launch_bounds__(256)
void conv_pack(const float* __restrict__ x,
               const float* __restrict__ WQ, const float* __restrict__ WK,
               const float* __restrict__ WV, const float* __restrict__ Wfc,
               const float* __restrict__ W1, const float* __restrict__ W2,
               const int* __restrict__ mask,
               __half* __restrict__ xh, __half* __restrict__ Wqkv,
               __half* __restrict__ Wfch, __half* __restrict__ W1h,
               __half* __restrict__ W2h, uint32_t* __restrict__ mpk)
{
    if (blockIdx.x >= CVT_BLOCKS) {
        int warp = (blockIdx.x - CVT_BLOCKS) * 8 + (threadIdx.x >> 5);
        int lane = threadIdx.x & 31;
        const int* rowp = mask + (size_t)warp * 1024;
        uint32_t*  outp = mpk  + (size_t)warp * 32;
        #pragma unroll
        for (int w = 0; w < 32; w++) {
            int v = rowp[w * 32 + lane];
            uint32_t word = __ballot_sync(0xffffffffu, v != 0);
            if (lane == 0) outp[w] = word;
        }
        return;
    }

    long long q = ((long long)blockIdx.x * 256 + threadIdx.x) * 4;
    const float* src;
    __half* dst;
    long long B = CVT_N0;
    if (q < B) {
        src = x + q; dst = xh + q;
    } else if (q < B + CVT_N1) {
        long long i = q - B; int row = (int)(i / Dx), col = (int)(i % Dx);
        src = WQ + i; dst = Wqkv + (size_t)row * 3 * Dx + col;
    } else if (q < B + 2*CVT_N1) {
        long long i = q - B - CVT_N1; int row = (int)(i / Dx), col = (int)(i % Dx);
        src = WK + i; dst = Wqkv + (size_t)row * 3 * Dx + Dx + col;
    } else if (q < B + 3*CVT_N1) {
        long long i = q - B - 2*CVT_N1; int row = (int)(i / Dx), col = (int)(i % Dx);
        src = WV + i; dst = Wqkv + (size_t)row * 3 * Dx + 2 * Dx + col;
    } else if (q < B + 4*CVT_N1) {
        long long i = q - B - 3*CVT_N1;
        src = Wfc + i; dst = Wfch + i;
    } else if (q < B + 4*CVT_N1 + CVT_N5) {
        long long i = q - B - 4*CVT_N1;
        src = W1 + i; dst = W1h + i;
    } else {
        long long i = q - B - 4*CVT_N1 - CVT_N5;
        src = W2 + i; dst = W2h + i;
    }
    float4 v = *(const float4*)src;
    *(uint32_t*)dst       = h2u(v.x, v.y);
    *(uint32_t*)(dst + 2) = h2u(v.z, v.w);
}

// ---------------- split-K reduce + residual + bias + LayerNorm --------------
template<int P, bool WH, bool BIAS>
__global__ __launch_bounds__(192)
void ln_kernel(const float* __restrict__ a, const float* __restrict__ r,
               const float* __restrict__ bias,
               const float* __restrict__ g, const float* __restrict__ be,
               float* __restrict__ out, __half* __restrict__ outh)
{
    const int tid = threadIdx.x;
    const size_t base = (size_t)blockIdx.x * Dx + tid * 4;

    float x0, x1, x2, x3;
    {
        float4 xr = *(const float4*)&r[base];
        x0 = xr.x; x1 = xr.y; x2 = xr.z; x3 = xr.w;
    }
    #pragma unroll
    for (int p = 0; p < P; p++) {
        float4 xa = *(const float4*)&a[(size_t)p * Mx * Dx + base];
        x0 += xa.x; x1 += xa.y; x2 += xa.z; x3 += xa.w;
    }
    if (BIAS) {
        float4 bv = *(const float4*)&bias[tid * 4];
        x0 += bv.x; x1 += bv.y; x2 += bv.z; x3 += bv.w;
    }

    float s = x0 + x1 + x2 + x3;
    float q = x0*x0 + x1*x1 + x2*x2 + x3*x3;
    #pragma unroll
    for (int o = 16; o; o >>= 1) {
        s += __shfl_xor_sync(0xffffffffu, s, o);
        q += __shfl_xor_sync(0xffffffffu, q, o);
    }
    __shared__ float ss[6], qq[6];
    if ((tid & 31) == 0) { ss[tid >> 5] = s; qq[tid >> 5] = q; }
    __syncthreads();
    if (tid == 0) {
        float S = 0.f, Qq = 0.f;
        #pragma unroll
        for (int w = 0; w < 6; w++) { S += ss[w]; Qq += qq[w]; }
        float mean = S * (1.f / Dx);
        float var  = Qq * (1.f / Dx) - mean * mean;
        ss[0] = mean;
        qq[0] = rsqrtf(var + EPSx);
    }
    __syncthreads();
    float mean = ss[0], rstd = qq[0];

    float4 gv = *(const float4*)&g[tid * 4];
    float4 bv = *(const float4*)&be[tid * 4];
    float4 o4;
    o4.x = (x0 - mean) * rstd * gv.x + bv.x;
    o4.y = (x1 - mean) * rstd * gv.y + bv.y;
    o4.z = (x2 - mean) * rstd * gv.z + bv.z;
    o4.w = (x3 - mean) * rstd * gv.w + bv.w;
    *(float4*)&out[base] = o4;
    if (WH) {
        *(uint32_t*)&outh[base]     = h2u(o4.x, o4.y);
        *(uint32_t*)&outh[base + 2] = h2u(o4.z, o4.w);
    }
}

// ---------------- launch ----------------------------------------------------
extern "C" void kernel_launch(void* const* d_in, const int* in_sizes, int n_in,
                              void* d_out, int out_size)
{
    const float* x    = (const float*)d_in[0];
    const int*   mask = (const int*)  d_in[1];
    const float* WQ   = (const float*)d_in[2];
    const float* WK   = (const float*)d_in[3];
    const float* WV   = (const float*)d_in[4];
    const float* Wfc  = (const float*)d_in[5];
    const float* W1   = (const float*)d_in[6];
    const float* b1   = (const float*)d_in[7];
    const float* W2   = (const float*)d_in[8];
    const float* b2   = (const float*)d_in[9];
    const float* g1   = (const float*)d_in[10];
    const float* be1  = (const float*)d_in[11];
    const float* g2   = (const float*)d_in[12];
    const float* be2  = (const float*)d_in[13];
    float* out = (float*)d_out;

    __half *xh, *QKVh, *atth, *nah, *lin1h;
    __half *Wqkv, *Wfch, *W1h, *W2h;
    float *proj2, *na, *lin2p;
    uint32_t* mpk;
    cudaGetSymbolAddress((void**)&xh,     g_xh);
    cudaGetSymbolAddress((void**)&QKVh,   g_QKVh);
    cudaGetSymbolAddress((void**)&mpk,    g_mpk);
    cudaGetSymbolAddress((void**)&atth,   g_atth);
    cudaGetSymbolAddress((void**)&proj2,  g_proj2);
    cudaGetSymbolAddress((void**)&na,     g_na);
    cudaGetSymbolAddress((void**)&nah,    g_nah);
    cudaGetSymbolAddress((void**)&lin1h,  g_lin1h);
    cudaGetSymbolAddress((void**)&lin2p,  g_lin2p);
    cudaGetSymbolAddress((void**)&Wqkv,   g_Wqkv);
    cudaGetSymbolAddress((void**)&Wfch,   g_Wfch);
    cudaGetSymbolAddress((void**)&W1h,    g_W1h);
    cudaGetSymbolAddress((void**)&W2h,    g_W2h);

    constexpr int SM128 = STAGES * (128 * PITCHA + 64 * PITCHB);   // 107520
    cudaFuncSetAttribute((void*)hgemm<128,3>, cudaFuncAttributeMaxDynamicSharedMemorySize, SM128);
    cudaFuncSetAttribute((void*)hgemm<128,7>, cudaFuncAttributeMaxDynamicSharedMemorySize, SM128);
    cudaFuncSetAttribute((void*)hgemm<128,8>, cudaFuncAttributeMaxDynamicSharedMemorySize, SM128);
    cudaFuncSetAttribute(flash_kernel, cudaFuncAttributeMaxDynamicSharedMemorySize, FSMEM);

    // fused conversions + mask packing
    conv_pack<<<CVT_BLOCKS + PK_BLOCKS, 256>>>(x, WQ, WK, WV, Wfc, W1, W2, mask,
                                               xh, Wqkv, Wfch, W1h, W2h, mpk);

    // fused QKV projection (M=4096, N=2304, K=768)
    hgemm<128,7><<<dim3(3*Dx/128, Mx/128), 256, SM128>>>(xh, Wqkv, nullptr, QKVh,
                                                         Dx, Dx, 3*Dx, Dx);

    // fused attention
    __half* Qh = QKVh;
    __half* Kh = QKVh + (size_t)Mx * Dx;
    __half* Vh = QKVh + (size_t)2 * Mx * Dx;
    flash_kernel<<<dim3(Sx/128, Bx*Hx), 256, FSMEM>>>(Qh, Kh, Vh, mpk, atth);

    // output projection: split-K=2 (384 CTAs), reduce fused into LN1
    hgemm<128,8><<<dim3(Dx/128, Mx/128, 2), 256, SM128>>>(atth, Wfch, nullptr, proj2,
                                                          Dx/2, Dx, Dx, Dx);
    ln_kernel<2,true,false><<<Mx, 192>>>(proj2, x, nullptr, g1, be1, na, nah);

    // FC1 (768 CTAs, full K)
    hgemm<128,3><<<dim3(FCx/128, Mx/128), 256, SM128>>>(nah, W1h, b1, lin1h,
                                                        Dx, Dx, FCx, FCx);
    // FC2: split-K=4 (768 CTAs), reduce + bias fused into LN2
    hgemm<128,8><<<dim3(Dx/128, Mx/128, 4), 256, SM128>>>(lin1h, W2h, nullptr, lin2p,
                                                          FCx/4, FCx, Dx, Dx);
    ln_kernel<4,false,true><<<Mx, 192>>>(lin2p, na, b2, g2, be2, out, nullptr);
}

// round 16
// speedup vs baseline: 1.0501x; 1.0501x over previous
#include <cuda_runtime.h>
#include <cuda_fp16.h>
#include <cstdint>
#include <cstddef>

// ---------------- problem dims ----------------
#define Bx 4
#define Sx 1024
#define Dx 768
#define Hx 12
#define HDx 64
#define FCx 3072
#define Mx (Bx*Sx)            // 4096
#define EPSx 1e-5f
#define INV_SQRT_H 0.28867513459481287f   // 1/sqrt(12)
#define LOG2E 1.4426950408889634f

// ---------------- scratch (static device globals) ----------------
__device__ __half   g_xh  [Mx*Dx];
__device__ __half   g_QKVh[(size_t)3*Mx*Dx];     // Q (pre-scaled, log2 domain) | K | V
__device__ uint32_t g_mpk [(size_t)Mx*32];       // packed mask bits
__device__ __half   g_atth[Mx*Dx];
__device__ float    g_proj2[(size_t)2*Mx*Dx];    // proj split-K partials
__device__ float    g_na  [Mx*Dx];
__device__ __half   g_nah [Mx*Dx];
__device__ __half   g_lin1h[(size_t)Mx*FCx];
__device__ float    g_lin2p[(size_t)4*Mx*Dx];    // FC2 split-K partials
__device__ __half   g_Wqkv[(size_t)Dx*3*Dx];     // [768][2304] row-major K x N
__device__ __half   g_Wfch[Dx*Dx];               // [768][768]
__device__ __half   g_W1h [(size_t)Dx*FCx];      // [768][3072]
__device__ __half   g_W2h [(size_t)FCx*Dx];      // [3072][768]

// ---------------- small helpers ----------------
__device__ __forceinline__ uint32_t smem_to_u32(const void* p) {
    uint32_t a;
    asm("{ .reg .u64 t; cvta.to.shared.u64 t, %1; cvt.u32.u64 %0, t; }" : "=r"(a) : "l"(p));
    return a;
}
__device__ __forceinline__ void cp16(uint32_t dst, const void* src) {
    asm volatile("cp.async.cg.shared.global [%0], [%1], 16;" :: "r"(dst), "l"(src));
}
#define CP_COMMIT() asm volatile("cp.async.commit_group;" ::: "memory")
template<int N> __device__ __forceinline__ void cp_wait() {
    asm volatile("cp.async.wait_group %0;" :: "n"(N) : "memory");
}
__device__ __forceinline__ void ldm_x4(uint32_t& r0, uint32_t& r1, uint32_t& r2, uint32_t& r3,
                                       uint32_t addr) {
    asm volatile("ldmatrix.sync.aligned.m8n8.x4.shared.b16 {%0,%1,%2,%3}, [%4];"
                 : "=r"(r0), "=r"(r1), "=r"(r2), "=r"(r3) : "r"(addr));
}
__device__ __forceinline__ void ldm_x4_t(uint32_t& r0, uint32_t& r1, uint32_t& r2, uint32_t& r3,
                                         uint32_t addr) {
    asm volatile("ldmatrix.sync.aligned.m8n8.x4.trans.shared.b16 {%0,%1,%2,%3}, [%4];"
                 : "=r"(r0), "=r"(r1), "=r"(r2), "=r"(r3) : "r"(addr));
}
__device__ __forceinline__ void mma16816(float* c, const uint32_t* a, uint32_t b0, uint32_t b1) {
    asm volatile(
        "mma.sync.aligned.m16n8k16.row.col.f32.f16.f16.f32 "
        "{%0,%1,%2,%3}, {%4,%5,%6,%7}, {%8,%9}, {%0,%1,%2,%3};"
        : "+f"(c[0]), "+f"(c[1]), "+f"(c[2]), "+f"(c[3])
        : "r"(a[0]), "r"(a[1]), "r"(a[2]), "r"(a[3]), "r"(b0), "r"(b1));
}
__device__ __forceinline__ uint32_t h2u(float a, float b) {
    __half2 h = __floats2half2_rn(a, b);
    return *(uint32_t*)&h;
}

// ---------------- fp16 TC GEMM: C[M,N] = A[M,K] * B[K,N] (B row-major) -----
// k-chunk 64, 3 stages, batched fragment loads per k16 step (R14 ordering).
// EPI: 3 fp16+bias+relu | 7 QKV route | 8 split-K partial
static constexpr int STAGES = 3;
static constexpr int PITCHA = 144;                // A: bytes per 64-half row
static constexpr int PITCHB = 272;                // B: bytes per 128-half k-row

template<int NT, int EPI>
__global__ __launch_bounds__(256)
void hgemm(const __half* __restrict__ A, const __half* __restrict__ Bm,
           const void* __restrict__ X, void* __restrict__ C0,
           int Kdim, int lda, int ldb, int ldc)
{
    constexpr int NTILES = NT / 16;
    constexpr int ABYTES = 128 * PITCHA;
    constexpr int BBYTES = 64 * PITCHB;
    constexpr int STB    = ABYTES + BBYTES;

    extern __shared__ __align__(128) char smem[];
    const uint32_t sb = smem_to_u32(smem);

    const int tid   = threadIdx.x;
    const int wid   = tid >> 5;
    const int lane  = tid & 31;
    const int warpM = wid & 3;
    const int warpN = wid >> 2;

    const int m0 = blockIdx.y * 128;
    const int n0 = blockIdx.x * NT;

    if (EPI == 8) {                 // K-slice offset for split-K
        A  += (size_t)blockIdx.z * Kdim;
        Bm += (size_t)blockIdx.z * Kdim * ldb;
    }

    float acc[2][NTILES][4];
    #pragma unroll
    for (int i = 0; i < 2; i++)
        #pragma unroll
        for (int j = 0; j < NTILES; j++)
            #pragma unroll
            for (int k = 0; k < 4; k++) acc[i][j][k] = 0.f;

    const int aRowOff = warpM * 32 + (lane & 7) + ((lane >> 3) & 1) * 8;
    const int aKOff   = (lane >> 4) * 8;
    const int bRow  = (lane & 7) + ((lane >> 3) & 1) * 8;
    const int bColB = ((lane >> 4) & 1) * 16;      // bytes

    const int nch = Kdim >> 6;                     // 64-wide chunks

    auto load_tiles = [&](int c, int s) {
        uint32_t baseA = sb + s * STB;
        uint32_t baseB = baseA + ABYTES;
        int k0 = c * 64;
        #pragma unroll
        for (int i = 0; i < 4; i++) {               // A: 128 rows x 64 halves
            int idx = tid + i * 256;
            int rr = idx >> 3, q = idx & 7;
            cp16(baseA + rr * PITCHA + q * 16,
                 A + (size_t)(m0 + rr) * lda + k0 + q * 8);
        }
        #pragma unroll
        for (int i = 0; i < NT / 32; i++) {         // B: 64 k-rows x NT halves
            int idx = tid + i * 256;
            int rr = idx >> 4, q = idx & 15;
            cp16(baseB + rr * PITCHB + q * 16,
                 Bm + (size_t)(k0 + rr) * ldb + n0 + q * 8);
        }
    };

    #pragma unroll
    for (int c = 0; c < STAGES - 1; c++) { load_tiles(c, c); CP_COMMIT(); }

    for (int c = 0; c < nch; c++) {
        cp_wait<STAGES - 2>();
        __syncthreads();

        int s = c % STAGES;
        uint32_t stA = sb + s * STB;
        uint32_t stB = stA + ABYTES;

        #pragma unroll
        for (int ks = 0; ks < 4; ks++) {           // 4 x k16 per chunk
            uint32_t a[2][4];
            #pragma unroll
            for (int mt = 0; mt < 2; mt++)
                ldm_x4(a[mt][0], a[mt][1], a[mt][2], a[mt][3],
                       stA + (aRowOff + mt * 16) * PITCHA + (ks * 16 + aKOff) * 2);
            uint32_t bf[NTILES / 2][4];
            #pragma unroll
            for (int ntp = 0; ntp < NTILES / 2; ntp++)
                ldm_x4_t(bf[ntp][0], bf[ntp][1], bf[ntp][2], bf[ntp][3],
                         stB + (ks * 16 + bRow) * PITCHB
                             + (warpN * (NT / 2) + ntp * 16) * 2 + bColB);
            #pragma unroll
            for (int ntp = 0; ntp < NTILES / 2; ntp++) {
                #pragma unroll
                for (int mt = 0; mt < 2; mt++) {
                    mma16816(acc[mt][ntp * 2 + 0], a[mt], bf[ntp][0], bf[ntp][1]);
                    mma16816(acc[mt][ntp * 2 + 1], a[mt], bf[ntp][2], bf[ntp][3]);
                }
            }
        }

        int cn = c + STAGES - 1;
        if (cn < nch) load_tiles(cn, cn % STAGES);
        CP_COMMIT();
    }

    const int rbase0 = m0 + warpM * 32 + (lane >> 2);
    const int cbase  = n0 + warpN * (NT / 2) + (lane & 3) * 2;

    #pragma unroll
    for (int mt = 0; mt < 2; mt++) {
        #pragma unroll
        for (int nt = 0; nt < NTILES; nt++) {
            int col = cbase + nt * 8;
            #pragma unroll
            for (int hf = 0; hf < 2; hf++) {
                int row = rbase0 + mt * 16 + hf * 8;
                float v0 = acc[mt][nt][hf * 2 + 0];
                float v1 = acc[mt][nt][hf * 2 + 1];
                if (EPI == 8) {
                    float* C = (float*)C0 + (size_t)blockIdx.z * Mx * ldc;
                    *(float2*)&C[(size_t)row * ldc + col] = make_float2(v0, v1);
                } else if (EPI == 7) {
                    __half* C = (__half*)C0;
                    int seg = (col >= 2 * Dx) ? 2 : (col >= Dx ? 1 : 0);
                    int cc  = col - seg * Dx;
                    float scl = (seg == 0) ? (INV_SQRT_H * LOG2E) : 1.f;
                    *(uint32_t*)&C[(size_t)seg * Mx * Dx + (size_t)row * Dx + cc] =
                        h2u(v0 * scl, v1 * scl);
                } else { // EPI == 3
                    const float* bias = (const float*)X;
                    __half* C = (__half*)C0;
                    float o0 = fmaxf(v0 + bias[col], 0.f);
                    float o1 = fmaxf(v1 + bias[col + 1], 0.f);
                    *(uint32_t*)&C[(size_t)row * ldc + col] = h2u(o0, o1);
                }
            }
        }
    }
}

// ---------------- flash attention: fused QK^T/mask/softmax/PV ---------------
// R14 structure (2-stage, loads after compute); paired fragment LDSMs.
static constexpr int FPIT  = 144;    // bytes per 64-half row
static constexpr int QBY   = 128 * FPIT;
static constexpr int TBY   = 64 * FPIT;
static constexpr int FSMEM = QBY + 4 * TBY;   // 55296

__global__ __launch_bounds__(256, 2)
void flash_kernel(const __half* __restrict__ Qg, const __half* __restrict__ Kg,
                  const __half* __restrict__ Vg, const uint32_t* __restrict__ mpk,
                  __half* __restrict__ Og)
{
    extern __shared__ __align__(128) char smem[];
    const uint32_t sQ = smem_to_u32(smem);
    const uint32_t sK = sQ + QBY;
    const uint32_t sV = sK + 2 * TBY;

    const int tid = threadIdx.x, wid = tid >> 5, lane = tid & 31;
    const int q0 = blockIdx.x * 128;
    const int z = blockIdx.y, b = z / Hx, h = z - b * Hx;

    const __half* Qp = Qg + ((size_t)b * Sx + q0) * Dx + h * HDx;
    const __half* Kp = Kg + ((size_t)b * Sx) * Dx + h * HDx;
    const __half* Vp = Vg + ((size_t)b * Sx) * Dx + h * HDx;
    const uint32_t* mp = mpk + ((size_t)b * Sx + q0) * 32;

    #pragma unroll
    for (int i = 0; i < 4; i++) {
        int idx = tid + i * 256;
        int r = idx >> 3, c = idx & 7;
        cp16(sQ + r * FPIT + c * 16, Qp + (size_t)r * Dx + c * 8);
    }
    auto loadKV = [&](int t, int s) {
        const __half* kb = Kp + (size_t)t * 64 * Dx;
        const __half* vb = Vp + (size_t)t * 64 * Dx;
        #pragma unroll
        for (int i = 0; i < 2; i++) {
            int idx = tid + i * 256;
            int r = idx >> 3, c = idx & 7;
            cp16(sK + s * TBY + r * FPIT + c * 16, kb + (size_t)r * Dx + c * 8);
            cp16(sV + s * TBY + r * FPIT + c * 16, vb + (size_t)r * Dx + c * 8);
        }
    };
    loadKV(0, 0); CP_COMMIT();
    loadKV(1, 1); CP_COMMIT();

    const int r  = lane >> 2;
    const int cq = lane & 3;
    const int rowL = wid * 16 + r;

    float acc_o[8][4];
    #pragma unroll
    for (int i = 0; i < 8; i++)
        #pragma unroll
        for (int j = 0; j < 4; j++) acc_o[i][j] = 0.f;
    float m0r = -1e30f, m1r = -1e30f, l0 = 0.f, l1 = 0.f;

    const uint32_t qAddrBase = sQ + (wid * 16 + (lane & 15)) * FPIT + (lane >> 4) * 16;
    const int kRow = (lane & 7) + ((lane >> 4) & 1) * 8;
    const int kColB = ((lane >> 3) & 1) * 16;
    const int vRow = (lane & 7) + ((lane >> 3) & 1) * 8;
    const int vColB = ((lane >> 4) & 1) * 16;

    for (int t = 0; t < 16; t++) {
        cp_wait<1>();
        __syncthreads();
        int s = t & 1;
        uint32_t stK = sK + s * TBY, stV = sV + s * TBY;

        float sc[8][4];
        #pragma unroll
        for (int i = 0; i < 8; i++)
            #pragma unroll
            for (int j = 0; j < 4; j++) sc[i][j] = 0.f;

        #pragma unroll
        for (int j = 0; j < 4; j++) {
            uint32_t qf[4];
            ldm_x4(qf[0], qf[1], qf[2], qf[3], qAddrBase + j * 32);
            #pragma unroll
            for (int npp = 0; npp < 2; npp++) {    // paired K-frag loads
                uint32_t k0f[4], k1f[4];
                ldm_x4(k0f[0], k0f[1], k0f[2], k0f[3],
                       stK + ((npp * 2 + 0) * 16 + kRow) * FPIT + j * 32 + kColB);
                ldm_x4(k1f[0], k1f[1], k1f[2], k1f[3],
                       stK + ((npp * 2 + 1) * 16 + kRow) * FPIT + j * 32 + kColB);
                mma16816(sc[npp * 4 + 0], qf, k0f[0], k0f[1]);
                mma16816(sc[npp * 4 + 1], qf, k0f[2], k0f[3]);
                mma16816(sc[npp * 4 + 2], qf, k1f[0], k1f[1]);
                mma16816(sc[npp * 4 + 3], qf, k1f[2], k1f[3]);
            }
        }

        const uint32_t mw0 = mp[(size_t)rowL * 32 + t * 2];
        const uint32_t mw1 = mp[(size_t)rowL * 32 + t * 2 + 1];
        const uint32_t nw0 = mp[(size_t)(rowL + 8) * 32 + t * 2];
        const uint32_t nw1 = mp[(size_t)(rowL + 8) * 32 + t * 2 + 1];
        #pragma unroll
        for (int nt = 0; nt < 8; nt++) {
            int colb = nt * 8 + 2 * cq;
            uint32_t wr  = (colb < 32) ? mw0 : mw1;
            uint32_t wr8 = (colb < 32) ? nw0 : nw1;
            int sh = colb & 31;
            sc[nt][0] = ((wr  >> sh)       & 1) ? sc[nt][0] : -1e9f;
            sc[nt][1] = ((wr  >> (sh + 1)) & 1) ? sc[nt][1] : -1e9f;
            sc[nt][2] = ((wr8 >> sh)       & 1) ? sc[nt][2] : -1e9f;
            sc[nt][3] = ((wr8 >> (sh + 1)) & 1) ? sc[nt][3] : -1e9f;
        }

        float mx0 = -1e30f, mx1 = -1e30f;
        #pragma unroll
        for (int nt = 0; nt < 8; nt++) {
            mx0 = fmaxf(mx0, fmaxf(sc[nt][0], sc[nt][1]));
            mx1 = fmaxf(mx1, fmaxf(sc[nt][2], sc[nt][3]));
        }
        mx0 = fmaxf(mx0, __shfl_xor_sync(0xffffffffu, mx0, 1));
        mx0 = fmaxf(mx0, __shfl_xor_sync(0xffffffffu, mx0, 2));
        mx1 = fmaxf(mx1, __shfl_xor_sync(0xffffffffu, mx1, 1));
        mx1 = fmaxf(mx1, __shfl_xor_sync(0xffffffffu, mx1, 2));

        float mn0 = fmaxf(m0r, mx0), mn1 = fmaxf(m1r, mx1);
        float f0 = exp2f(m0r - mn0), f1 = exp2f(m1r - mn1);
        m0r = mn0; m1r = mn1;

        float s0 = 0.f, s1 = 0.f;
        #pragma unroll
        for (int nt = 0; nt < 8; nt++) {
            sc[nt][0] = exp2f(sc[nt][0] - mn0);
            sc[nt][1] = exp2f(sc[nt][1] - mn0);
            sc[nt][2] = exp2f(sc[nt][2] - mn1);
            sc[nt][3] = exp2f(sc[nt][3] - mn1);
            s0 += sc[nt][0] + sc[nt][1];
            s1 += sc[nt][2] + sc[nt][3];
        }
        s0 += __shfl_xor_sync(0xffffffffu, s0, 1);
        s0 += __shfl_xor_sync(0xffffffffu, s0, 2);
        s1 += __shfl_xor_sync(0xffffffffu, s1, 1);
        s1 += __shfl_xor_sync(0xffffffffu, s1, 2);
        l0 = l0 * f0 + s0;
        l1 = l1 * f1 + s1;

        #pragma unroll
        for (int nt = 0; nt < 8; nt++) {
            acc_o[nt][0] *= f0; acc_o[nt][1] *= f0;
            acc_o[nt][2] *= f1; acc_o[nt][3] *= f1;
        }

        uint32_t ph[4][4];
        #pragma unroll
        for (int j = 0; j < 4; j++) {
            ph[j][0] = h2u(sc[2*j  ][0], sc[2*j  ][1]);
            ph[j][1] = h2u(sc[2*j  ][2], sc[2*j  ][3]);
            ph[j][2] = h2u(sc[2*j+1][0], sc[2*j+1][1]);
            ph[j][3] = h2u(sc[2*j+1][2], sc[2*j+1][3]);
        }
        #pragma unroll
        for (int j = 0; j < 4; j++) {
            #pragma unroll
            for (int nnp = 0; nnp < 2; nnp++) {    // paired V-frag loads
                uint32_t v0f[4], v1f[4];
                ldm_x4_t(v0f[0], v0f[1], v0f[2], v0f[3],
                         stV + (j * 16 + vRow) * FPIT + (nnp * 2 + 0) * 32 + vColB);
                ldm_x4_t(v1f[0], v1f[1], v1f[2], v1f[3],
                         stV + (j * 16 + vRow) * FPIT + (nnp * 2 + 1) * 32 + vColB);
                mma16816(acc_o[nnp * 4 + 0], ph[j], v0f[0], v0f[1]);
                mma16816(acc_o[nnp * 4 + 1], ph[j], v0f[2], v0f[3]);
                mma16816(acc_o[nnp * 4 + 2], ph[j], v1f[0], v1f[1]);
                mma16816(acc_o[nnp * 4 + 3], ph[j], v1f[2], v1f[3]);
            }
        }

        __syncthreads();
        if (t + 2 < 16) loadKV(t + 2, s);
        CP_COMMIT();
    }

    float i0 = 1.f / l0, i1 = 1.f / l1;
    __half* Op = Og + ((size_t)b * Sx + q0 + wid * 16) * Dx + h * HDx;
    #pragma unroll
    for (int nt = 0; nt < 8; nt++) {
        int col = nt * 8 + 2 * cq;
        *(uint32_t*)&Op[(size_t)r * Dx + col] =
            h2u(acc_o[nt][0] * i0, acc_o[nt][1] * i0);
        *(uint32_t*)&Op[(size_t)(r + 8) * Dx + col] =
            h2u(acc_o[nt][2] * i1, acc_o[nt][3] * i1);
    }
}

// ---------------- fused fp32->fp16 conversions + mask bit-packing -----------
#define CVT_N0 (Mx*Dx)
#define CVT_N1 (Dx*Dx)
#define CVT_N5 (Dx*FCx)
#define CVT_TOT (CVT_N0 + 4*CVT_N1 + 2*CVT_N5)   // 10,223,616
#define CVT_BLOCKS (CVT_TOT / 4 / 256)           // 9984
#define PK_BLOCKS (Mx / 8)                       // 512

__global__ __launch_bounds__(256)
void conv_pack(const float* __restrict__ x,
               const float* __restrict__ WQ, const float* __restrict__ WK,
               const float* __restrict__ WV, const float* __restrict__ Wfc,
               const float* __restrict__ W1, const float* __restrict__ W2,
               const int* __restrict__ mask,
               __half* __restrict__ xh, __half* __restrict__ Wqkv,
               __half* __restrict__ Wfch, __half* __restrict__ W1h,
               __half* __restrict__ W2h, uint32_t* __restrict__ mpk)
{
    if (blockIdx.x >= CVT_BLOCKS) {
        int warp = (blockIdx.x - CVT_BLOCKS) * 8 + (threadIdx.x >> 5);
        int lane = threadIdx.x & 31;
        const int* rowp = mask + (size_t)warp * 1024;
        uint32_t*  outp = mpk  + (size_t)warp * 32;
        #pragma unroll
        for (int w = 0; w < 32; w++) {
            int v = rowp[w * 32 + lane];
            uint32_t word = __ballot_sync(0xffffffffu, v != 0);
            if (lane == 0) outp[w] = word;
        }
        return;
    }

    long long q = ((long long)blockIdx.x * 256 + threadIdx.x) * 4;
    const float* src;
    __half* dst;
    long long B = CVT_N0;
    if (q < B) {
        src = x + q; dst = xh + q;
    } else if (q < B + CVT_N1) {
        long long i = q - B; int row = (int)(i / Dx), col = (int)(i % Dx);
        src = WQ + i; dst = Wqkv + (size_t)row * 3 * Dx + col;
    } else if (q < B + 2*CVT_N1) {
        long long i = q - B - CVT_N1; int row = (int)(i / Dx), col = (int)(i % Dx);
        src = WK + i; dst = Wqkv + (size_t)row * 3 * Dx + Dx + col;
    } else if (q < B + 3*CVT_N1) {
        long long i = q - B - 2*CVT_N1; int row = (int)(i / Dx), col = (int)(i % Dx);
        src = WV + i; dst = Wqkv + (size_t)row * 3 * Dx + 2 * Dx + col;
    } else if (q < B + 4*CVT_N1) {
        long long i = q - B - 3*CVT_N1;
        src = Wfc + i; dst = Wfch + i;
    } else if (q < B + 4*CVT_N1 + CVT_N5) {
        long long i = q - B - 4*CVT_N1;
        src = W1 + i; dst = W1h + i;
    } else {
        long long i = q - B - 4*CVT_N1 - CVT_N5;
        src = W2 + i; dst = W2h + i;
    }
    float4 v = *(const float4*)src;
    *(uint32_t*)dst       = h2u(v.x, v.y);
    *(uint32_t*)(dst + 2) = h2u(v.z, v.w);
}

// ---------------- split-K reduce + residual + bias + LayerNorm --------------
template<int P, bool WH, bool BIAS>
__global__ __launch_bounds__(192)
void ln_kernel(const float* __restrict__ a, const float* __restrict__ r,
               const float* __restrict__ bias,
               const float* __restrict__ g, const float* __restrict__ be,
               float* __restrict__ out, __half* __restrict__ outh)
{
    const int tid = threadIdx.x;
    const size_t base = (size_t)blockIdx.x * Dx + tid * 4;

    float x0, x1, x2, x3;
    {
        float4 xr = *(const float4*)&r[base];
        x0 = xr.x; x1 = xr.y; x2 = xr.z; x3 = xr.w;
    }
    #pragma unroll
    for (int p = 0; p < P; p++) {
        float4 xa = *(const float4*)&a[(size_t)p * Mx * Dx + base];
        x0 += xa.x; x1 += xa.y; x2 += xa.z; x3 += xa.w;
    }
    if (BIAS) {
        float4 bv = *(const float4*)&bias[tid * 4];
        x0 += bv.x; x1 += bv.y; x2 += bv.z; x3 += bv.w;
    }

    float s = x0 + x1 + x2 + x3;
    float q = x0*x0 + x1*x1 + x2*x2 + x3*x3;
    #pragma unroll
    for (int o = 16; o; o >>= 1) {
        s += __shfl_xor_sync(0xffffffffu, s, o);
        q += __shfl_xor_sync(0xffffffffu, q, o);
    }
    __shared__ float ss[6], qq[6];
    if ((tid & 31) == 0) { ss[tid >> 5] = s; qq[tid >> 5] = q; }
    __syncthreads();
    if (tid == 0) {
        float S = 0.f, Qq = 0.f;
        #pragma unroll
        for (int w = 0; w < 6; w++) { S += ss[w]; Qq += qq[w]; }
        float mean = S * (1.f / Dx);
        float var  = Qq * (1.f / Dx) - mean * mean;
        ss[0] = mean;
        qq[0] = rsqrtf(var + EPSx);
    }
    __syncthreads();
    float mean = ss[0], rstd = qq[0];

    float4 gv = *(const float4*)&g[tid * 4];
    float4 bv = *(const float4*)&be[tid * 4];
    float4 o4;
    o4.x = (x0 - mean) * rstd * gv.x + bv.x;
    o4.y = (x1 - mean) * rstd * gv.y + bv.y;
    o4.z = (x2 - mean) * rstd * gv.z + bv.z;
    o4.w = (x3 - mean) * rstd * gv.w + bv.w;
    *(float4*)&out[base] = o4;
    if (WH) {
        *(uint32_t*)&outh[base]     = h2u(o4.x, o4.y);
        *(uint32_t*)&outh[base + 2] = h2u(o4.z, o4.w);
    }
}

// ---------------- launch ----------------------------------------------------
extern "C" void kernel_launch(void* const* d_in, const int* in_sizes, int n_in,
                              void* d_out, int out_size)
{
    const float* x    = (const float*)d_in[0];
    const int*   mask = (const int*)  d_in[1];
    const float* WQ   = (const float*)d_in[2];
    const float* WK   = (const float*)d_in[3];
    const float* WV   = (const float*)d_in[4];
    const float* Wfc  = (const float*)d_in[5];
    const float* W1   = (const float*)d_in[6];
    const float* b1   = (const float*)d_in[7];
    const float* W2   = (const float*)d_in[8];
    const float* b2   = (const float*)d_in[9];
    const float* g1   = (const float*)d_in[10];
    const float* be1  = (const float*)d_in[11];
    const float* g2   = (const float*)d_in[12];
    const float* be2  = (const float*)d_in[13];
    float* out = (float*)d_out;

    __half *xh, *QKVh, *atth, *nah, *lin1h;
    __half *Wqkv, *Wfch, *W1h, *W2h;
    float *proj2, *na, *lin2p;
    uint32_t* mpk;
    cudaGetSymbolAddress((void**)&xh,     g_xh);
    cudaGetSymbolAddress((void**)&QKVh,   g_QKVh);
    cudaGetSymbolAddress((void**)&mpk,    g_mpk);
    cudaGetSymbolAddress((void**)&atth,   g_atth);
    cudaGetSymbolAddress((void**)&proj2,  g_proj2);
    cudaGetSymbolAddress((void**)&na,     g_na);
    cudaGetSymbolAddress((void**)&nah,    g_nah);
    cudaGetSymbolAddress((void**)&lin1h,  g_lin1h);
    cudaGetSymbolAddress((void**)&lin2p,  g_lin2p);
    cudaGetSymbolAddress((void**)&Wqkv,   g_Wqkv);
    cudaGetSymbolAddress((void**)&Wfch,   g_Wfch);
    cudaGetSymbolAddress((void**)&W1h,    g_W1h);
    cudaGetSymbolAddress((void**)&W2h,    g_W2h);

    constexpr int SM128 = STAGES * (128 * PITCHA + 64 * PITCHB);   // 107520
    cudaFuncSetAttribute((void*)hgemm<128,3>, cudaFuncAttributeMaxDynamicSharedMemorySize, SM128);
    cudaFuncSetAttribute((void*)hgemm<128,7>, cudaFuncAttributeMaxDynamicSharedMemorySize, SM128);
    cudaFuncSetAttribute((void*)hgemm<128,8>, cudaFuncAttributeMaxDynamicSharedMemorySize, SM128);
    cudaFuncSetAttribute(flash_kernel, cudaFuncAttributeMaxDynamicSharedMemorySize, FSMEM);

    // fused conversions + mask packing
    conv_pack<<<CVT_BLOCKS + PK_BLOCKS, 256>>>(x, WQ, WK, WV, Wfc, W1, W2, mask,
                                               xh, Wqkv, Wfch, W1h, W2h, mpk);

    // fused QKV projection (M=4096, N=2304, K=768)
    hgemm<128,7><<<dim3(3*Dx/128, Mx/128), 256, SM128>>>(xh, Wqkv, nullptr, QKVh,
                                                         Dx, Dx, 3*Dx, Dx);

    // fused attention
    __half* Qh = QKVh;
    __half* Kh = QKVh + (size_t)Mx * Dx;
    __half* Vh = QKVh + (size_t)2 * Mx * Dx;
    flash_kernel<<<dim3(Sx/128, Bx*Hx), 256, FSMEM>>>(Qh, Kh, Vh, mpk, atth);

    // output projection: split-K=2 (384 CTAs), reduce fused into LN1
    hgemm<128,8><<<dim3(Dx/128, Mx/128, 2), 256, SM128>>>(atth, Wfch, nullptr, proj2,
                                                          Dx/2, Dx, Dx, Dx);
    ln_kernel<2,true,false><<<Mx, 192>>>(proj2, x, nullptr, g1, be1, na, nah);

    // FC1 (768 CTAs, full K)
    hgemm<128,3><<<dim3(FCx/128, Mx/128), 256, SM128>>>(nah, W1h, b1, lin1h,
                                                        Dx, Dx, FCx, FCx);
    // FC2: split-K=4 (768 CTAs), reduce + bias fused into LN2
    hgemm<128,8><<<dim3(Dx/128, Mx/128, 4), 256, SM128>>>(lin1h, W2h, nullptr, lin2p,
                                                          FCx/4, FCx, Dx, Dx);
    ln_kernel<4,false,true><<<Mx, 192>>>(lin2p, na, b2, g2, be2, out, nullptr);
}

// round 17
// speedup vs baseline: 1.0730x; 1.0217x over previous
#include <cuda_runtime.h>
#include <cuda_fp16.h>
#include <cstdint>
#include <cstddef>

// ---------------- problem dims ----------------
#define Bx 4
#define Sx 1024
#define Dx 768
#define Hx 12
#define HDx 64
#define FCx 3072
#define Mx (Bx*Sx)            // 4096
#define EPSx 1e-5f
#define INV_SQRT_H 0.28867513459481287f   // 1/sqrt(12)
#define LOG2E 1.4426950408889634f

// ---------------- scratch (static device globals) ----------------
__device__ __half   g_xh  [Mx*Dx];
__device__ __half   g_QKVh[(size_t)3*Mx*Dx];     // Q (pre-scaled, log2 domain) | K | V
__device__ uint32_t g_mpk [(size_t)Mx*32];       // packed mask bits
__device__ __half   g_atth[Mx*Dx];
__device__ float    g_proj2[(size_t)3*Mx*Dx];    // proj split-K partials
__device__ float    g_na  [Mx*Dx];
__device__ __half   g_nah [Mx*Dx];
__device__ __half   g_lin1h[(size_t)Mx*FCx];
__device__ float    g_lin2p[(size_t)3*Mx*Dx];    // FC2 split-K partials
__device__ __half   g_Wqkv[(size_t)Dx*3*Dx];     // [768][2304] row-major K x N
__device__ __half   g_Wfch[Dx*Dx];               // [768][768]
__device__ __half   g_W1h [(size_t)Dx*FCx];      // [768][3072]
__device__ __half   g_W2h [(size_t)FCx*Dx];      // [3072][768]

// ---------------- small helpers ----------------
__device__ __forceinline__ uint32_t smem_to_u32(const void* p) {
    uint32_t a;
    asm("{ .reg .u64 t; cvta.to.shared.u64 t, %1; cvt.u32.u64 %0, t; }" : "=r"(a) : "l"(p));
    return a;
}
__device__ __forceinline__ void cp16(uint32_t dst, const void* src) {
    asm volatile("cp.async.cg.shared.global [%0], [%1], 16;" :: "r"(dst), "l"(src));
}
#define CP_COMMIT() asm volatile("cp.async.commit_group;" ::: "memory")
template<int N> __device__ __forceinline__ void cp_wait() {
    asm volatile("cp.async.wait_group %0;" :: "n"(N) : "memory");
}
__device__ __forceinline__ void ldm_x4(uint32_t& r0, uint32_t& r1, uint32_t& r2, uint32_t& r3,
                                       uint32_t addr) {
    asm volatile("ldmatrix.sync.aligned.m8n8.x4.shared.b16 {%0,%1,%2,%3}, [%4];"
                 : "=r"(r0), "=r"(r1), "=r"(r2), "=r"(r3) : "r"(addr));
}
__device__ __forceinline__ void ldm_x4_t(uint32_t& r0, uint32_t& r1, uint32_t& r2, uint32_t& r3,
                                         uint32_t addr) {
    asm volatile("ldmatrix.sync.aligned.m8n8.x4.trans.shared.b16 {%0,%1,%2,%3}, [%4];"
                 : "=r"(r0), "=r"(r1), "=r"(r2), "=r"(r3) : "r"(addr));
}
__device__ __forceinline__ void mma16816(float* c, const uint32_t* a, uint32_t b0, uint32_t b1) {
    asm volatile(
        "mma.sync.aligned.m16n8k16.row.col.f32.f16.f16.f32 "
        "{%0,%1,%2,%3}, {%4,%5,%6,%7}, {%8,%9}, {%0,%1,%2,%3};"
        : "+f"(c[0]), "+f"(c[1]), "+f"(c[2]), "+f"(c[3])
        : "r"(a[0]), "r"(a[1]), "r"(a[2]), "r"(a[3]), "r"(b0), "r"(b1));
}
__device__ __forceinline__ uint32_t h2u(float a, float b) {
    __half2 h = __floats2half2_rn(a, b);
    return *(uint32_t*)&h;
}

// ---------------- fp16 TC GEMM: C[M,N] = A[M,K] * B[K,N] (B row-major) -----
// k-chunk 64, 3 stages, batched fragment loads per k16 step.
// EPI: 3 fp16+bias+relu | 7 QKV route | 8 split-K partial
static constexpr int STAGES = 3;
static constexpr int PITCHA = 144;                // A: bytes per 64-half row
static constexpr int PITCHB = 272;                // B: bytes per 128-half k-row

template<int NT, int EPI>
__global__ __launch_bounds__(256)
void hgemm(const __half* __restrict__ A, const __half* __restrict__ Bm,
           const void* __restrict__ X, void* __restrict__ C0,
           int Kdim, int lda, int ldb, int ldc)
{
    constexpr int NTILES = NT / 16;
    constexpr int ABYTES = 128 * PITCHA;
    constexpr int BBYTES = 64 * PITCHB;
    constexpr int STB    = ABYTES + BBYTES;

    extern __shared__ __align__(128) char smem[];
    const uint32_t sb = smem_to_u32(smem);

    const int tid   = threadIdx.x;
    const int wid   = tid >> 5;
    const int lane  = tid & 31;
    const int warpM = wid & 3;
    const int warpN = wid >> 2;

    const int m0 = blockIdx.y * 128;
    const int n0 = blockIdx.x * NT;

    if (EPI == 8) {                 // K-slice offset for split-K
        A  += (size_t)blockIdx.z * Kdim;
        Bm += (size_t)blockIdx.z * Kdim * ldb;
    }

    float acc[2][NTILES][4];
    #pragma unroll
    for (int i = 0; i < 2; i++)
        #pragma unroll
        for (int j = 0; j < NTILES; j++)
            #pragma unroll
            for (int k = 0; k < 4; k++) acc[i][j][k] = 0.f;

    const int aRowOff = warpM * 32 + (lane & 7) + ((lane >> 3) & 1) * 8;
    const int aKOff   = (lane >> 4) * 8;
    const int bRow  = (lane & 7) + ((lane >> 3) & 1) * 8;
    const int bColB = ((lane >> 4) & 1) * 16;      // bytes

    const int nch = Kdim >> 6;                     // 64-wide chunks

    auto load_tiles = [&](int c, int s) {
        uint32_t baseA = sb + s * STB;
        uint32_t baseB = baseA + ABYTES;
        int k0 = c * 64;
        #pragma unroll
        for (int i = 0; i < 4; i++) {               // A: 128 rows x 64 halves
            int idx = tid + i * 256;
            int rr = idx >> 3, q = idx & 7;
            cp16(baseA + rr * PITCHA + q * 16,
                 A + (size_t)(m0 + rr) * lda + k0 + q * 8);
        }
        #pragma unroll
        for (int i = 0; i < NT / 32; i++) {         // B: 64 k-rows x NT halves
            int idx = tid + i * 256;
            int rr = idx >> 4, q = idx & 15;
            cp16(baseB + rr * PITCHB + q * 16,
                 Bm + (size_t)(k0 + rr) * ldb + n0 + q * 8);
        }
    };

    #pragma unroll
    for (int c = 0; c < STAGES - 1; c++) { load_tiles(c, c); CP_COMMIT(); }

    for (int c = 0; c < nch; c++) {
        cp_wait<STAGES - 2>();
        __syncthreads();

        int s = c % STAGES;
        uint32_t stA = sb + s * STB;
        uint32_t stB = stA + ABYTES;

        #pragma unroll
        for (int ks = 0; ks < 4; ks++) {           // 4 x k16 per chunk
            uint32_t a[2][4];
            #pragma unroll
            for (int mt = 0; mt < 2; mt++)
                ldm_x4(a[mt][0], a[mt][1], a[mt][2], a[mt][3],
                       stA + (aRowOff + mt * 16) * PITCHA + (ks * 16 + aKOff) * 2);
            uint32_t bf[NTILES / 2][4];
            #pragma unroll
            for (int ntp = 0; ntp < NTILES / 2; ntp++)
                ldm_x4_t(bf[ntp][0], bf[ntp][1], bf[ntp][2], bf[ntp][3],
                         stB + (ks * 16 + bRow) * PITCHB
                             + (warpN * (NT / 2) + ntp * 16) * 2 + bColB);
            #pragma unroll
            for (int ntp = 0; ntp < NTILES / 2; ntp++) {
                #pragma unroll
                for (int mt = 0; mt < 2; mt++) {
                    mma16816(acc[mt][ntp * 2 + 0], a[mt], bf[ntp][0], bf[ntp][1]);
                    mma16816(acc[mt][ntp * 2 + 1], a[mt], bf[ntp][2], bf[ntp][3]);
                }
            }
        }

        int cn = c + STAGES - 1;
        if (cn < nch) load_tiles(cn, cn % STAGES);
        CP_COMMIT();
    }

    const int rbase0 = m0 + warpM * 32 + (lane >> 2);
    const int cbase  = n0 + warpN * (NT / 2) + (lane & 3) * 2;

    #pragma unroll
    for (int mt = 0; mt < 2; mt++) {
        #pragma unroll
        for (int nt = 0; nt < NTILES; nt++) {
            int col = cbase + nt * 8;
            #pragma unroll
            for (int hf = 0; hf < 2; hf++) {
                int row = rbase0 + mt * 16 + hf * 8;
                float v0 = acc[mt][nt][hf * 2 + 0];
                float v1 = acc[mt][nt][hf * 2 + 1];
                if (EPI == 8) {
                    float* C = (float*)C0 + (size_t)blockIdx.z * Mx * ldc;
                    *(float2*)&C[(size_t)row * ldc + col] = make_float2(v0, v1);
                } else if (EPI == 7) {
                    __half* C = (__half*)C0;
                    int seg = (col >= 2 * Dx) ? 2 : (col >= Dx ? 1 : 0);
                    int cc  = col - seg * Dx;
                    float scl = (seg == 0) ? (INV_SQRT_H * LOG2E) : 1.f;
                    *(uint32_t*)&C[(size_t)seg * Mx * Dx + (size_t)row * Dx + cc] =
                        h2u(v0 * scl, v1 * scl);
                } else { // EPI == 3
                    const float* bias = (const float*)X;
                    __half* C = (__half*)C0;
                    float o0 = fmaxf(v0 + bias[col], 0.f);
                    float o1 = fmaxf(v1 + bias[col + 1], 0.f);
                    *(uint32_t*)&C[(size_t)row * ldc + col] = h2u(o0, o1);
                }
            }
        }
    }
}

// ---------------- flash attention: fused QK^T/mask/softmax/PV ---------------
// 2-stage, loads after compute, paired fragment LDSMs.
static constexpr int FPIT  = 144;    // bytes per 64-half row
static constexpr int QBY   = 128 * FPIT;
static constexpr int TBY   = 64 * FPIT;
static constexpr int FSMEM = QBY + 4 * TBY;   // 55296

__global__ __launch_bounds__(256, 2)
void flash_kernel(const __half* __restrict__ Qg, const __half* __restrict__ Kg,
                  const __half* __restrict__ Vg, const uint32_t* __restrict__ mpk,
                  __half* __restrict__ Og)
{
    extern __shared__ __align__(128) char smem[];
    const uint32_t sQ = smem_to_u32(smem);
    const uint32_t sK = sQ + QBY;
    const uint32_t sV = sK + 2 * TBY;

    const int tid = threadIdx.x, wid = tid >> 5, lane = tid & 31;
    const int q0 = blockIdx.x * 128;
    const int z = blockIdx.y, b = z / Hx, h = z - b * Hx;

    const __half* Qp = Qg + ((size_t)b * Sx + q0) * Dx + h * HDx;
    const __half* Kp = Kg + ((size_t)b * Sx) * Dx + h * HDx;
    const __half* Vp = Vg + ((size_t)b * Sx) * Dx + h * HDx;
    const uint32_t* mp = mpk + ((size_t)b * Sx + q0) * 32;

    #pragma unroll
    for (int i = 0; i < 4; i++) {
        int idx = tid + i * 256;
        int r = idx >> 3, c = idx & 7;
        cp16(sQ + r * FPIT + c * 16, Qp + (size_t)r * Dx + c * 8);
    }
    auto loadKV = [&](int t, int s) {
        const __half* kb = Kp + (size_t)t * 64 * Dx;
        const __half* vb = Vp + (size_t)t * 64 * Dx;
        #pragma unroll
        for (int i = 0; i < 2; i++) {
            int idx = tid + i * 256;
            int r = idx >> 3, c = idx & 7;
            cp16(sK + s * TBY + r * FPIT + c * 16, kb + (size_t)r * Dx + c * 8);
            cp16(sV + s * TBY + r * FPIT + c * 16, vb + (size_t)r * Dx + c * 8);
        }
    };
    loadKV(0, 0); CP_COMMIT();
    loadKV(1, 1); CP_COMMIT();

    const int r  = lane >> 2;
    const int cq = lane & 3;
    const int rowL = wid * 16 + r;

    float acc_o[8][4];
    #pragma unroll
    for (int i = 0; i < 8; i++)
        #pragma unroll
        for (int j = 0; j < 4; j++) acc_o[i][j] = 0.f;
    float m0r = -1e30f, m1r = -1e30f, l0 = 0.f, l1 = 0.f;

    const uint32_t qAddrBase = sQ + (wid * 16 + (lane & 15)) * FPIT + (lane >> 4) * 16;
    const int kRow = (lane & 7) + ((lane >> 4) & 1) * 8;
    const int kColB = ((lane >> 3) & 1) * 16;
    const int vRow = (lane & 7) + ((lane >> 3) & 1) * 8;
    const int vColB = ((lane >> 4) & 1) * 16;

    for (int t = 0; t < 16; t++) {
        cp_wait<1>();
        __syncthreads();
        int s = t & 1;
        uint32_t stK = sK + s * TBY, stV = sV + s * TBY;

        float sc[8][4];
        #pragma unroll
        for (int i = 0; i < 8; i++)
            #pragma unroll
            for (int j = 0; j < 4; j++) sc[i][j] = 0.f;

        #pragma unroll
        for (int j = 0; j < 4; j++) {
            uint32_t qf[4];
            ldm_x4(qf[0], qf[1], qf[2], qf[3], qAddrBase + j * 32);
            #pragma unroll
            for (int npp = 0; npp < 2; npp++) {    // paired K-frag loads
                uint32_t k0f[4], k1f[4];
                ldm_x4(k0f[0], k0f[1], k0f[2], k0f[3],
                       stK + ((npp * 2 + 0) * 16 + kRow) * FPIT + j * 32 + kColB);
                ldm_x4(k1f[0], k1f[1], k1f[2], k1f[3],
                       stK + ((npp * 2 + 1) * 16 + kRow) * FPIT + j * 32 + kColB);
                mma16816(sc[npp * 4 + 0], qf, k0f[0], k0f[1]);
                mma16816(sc[npp * 4 + 1], qf, k0f[2], k0f[3]);
                mma16816(sc[npp * 4 + 2], qf, k1f[0], k1f[1]);
                mma16816(sc[npp * 4 + 3], qf, k1f[2], k1f[3]);
            }
        }

        const uint32_t mw0 = mp[(size_t)rowL * 32 + t * 2];
        const uint32_t mw1 = mp[(size_t)rowL * 32 + t * 2 + 1];
        const uint32_t nw0 = mp[(size_t)(rowL + 8) * 32 + t * 2];
        const uint32_t nw1 = mp[(size_t)(rowL + 8) * 32 + t * 2 + 1];
        #pragma unroll
        for (int nt = 0; nt < 8; nt++) {
            int colb = nt * 8 + 2 * cq;
            uint32_t wr  = (colb < 32) ? mw0 : mw1;
            uint32_t wr8 = (colb < 32) ? nw0 : nw1;
            int sh = colb & 31;
            sc[nt][0] = ((wr  >> sh)       & 1) ? sc[nt][0] : -1e9f;
            sc[nt][1] = ((wr  >> (sh + 1)) & 1) ? sc[nt][1] : -1e9f;
            sc[nt][2] = ((wr8 >> sh)       & 1) ? sc[nt][2] : -1e9f;
            sc[nt][3] = ((wr8 >> (sh + 1)) & 1) ? sc[nt][3] : -1e9f;
        }

        float mx0 = -1e30f, mx1 = -1e30f;
        #pragma unroll
        for (int nt = 0; nt < 8; nt++) {
            mx0 = fmaxf(mx0, fmaxf(sc[nt][0], sc[nt][1]));
            mx1 = fmaxf(mx1, fmaxf(sc[nt][2], sc[nt][3]));
        }
        mx0 = fmaxf(mx0, __shfl_xor_sync(0xffffffffu, mx0, 1));
        mx0 = fmaxf(mx0, __shfl_xor_sync(0xffffffffu, mx0, 2));
        mx1 = fmaxf(mx1, __shfl_xor_sync(0xffffffffu, mx1, 1));
        mx1 = fmaxf(mx1, __shfl_xor_sync(0xffffffffu, mx1, 2));

        float mn0 = fmaxf(m0r, mx0), mn1 = fmaxf(m1r, mx1);
        float f0 = exp2f(m0r - mn0), f1 = exp2f(m1r - mn1);
        m0r = mn0; m1r = mn1;

        float s0 = 0.f, s1 = 0.f;
        #pragma unroll
        for (int nt = 0; nt < 8; nt++) {
            sc[nt][0] = exp2f(sc[nt][0] - mn0);
            sc[nt][1] = exp2f(sc[nt][1] - mn0);
            sc[nt][2] = exp2f(sc[nt][2] - mn1);
            sc[nt][3] = exp2f(sc[nt][3] - mn1);
            s0 += sc[nt][0] + sc[nt][1];
            s1 += sc[nt][2] + sc[nt][3];
        }
        s0 += __shfl_xor_sync(0xffffffffu, s0, 1);
        s0 += __shfl_xor_sync(0xffffffffu, s0, 2);
        s1 += __shfl_xor_sync(0xffffffffu, s1, 1);
        s1 += __shfl_xor_sync(0xffffffffu, s1, 2);
        l0 = l0 * f0 + s0;
        l1 = l1 * f1 + s1;

        #pragma unroll
        for (int nt = 0; nt < 8; nt++) {
            acc_o[nt][0] *= f0; acc_o[nt][1] *= f0;
            acc_o[nt][2] *= f1; acc_o[nt][3] *= f1;
        }

        uint32_t ph[4][4];
        #pragma unroll
        for (int j = 0; j < 4; j++) {
            ph[j][0] = h2u(sc[2*j  ][0], sc[2*j  ][1]);
            ph[j][1] = h2u(sc[2*j  ][2], sc[2*j  ][3]);
            ph[j][2] = h2u(sc[2*j+1][0], sc[2*j+1][1]);
            ph[j][3] = h2u(sc[2*j+1][2], sc[2*j+1][3]);
        }
        #pragma unroll
        for (int j = 0; j < 4; j++) {
            #pragma unroll
            for (int nnp = 0; nnp < 2; nnp++) {    // paired V-frag loads
                uint32_t v0f[4], v1f[4];
                ldm_x4_t(v0f[0], v0f[1], v0f[2], v0f[3],
                         stV + (j * 16 + vRow) * FPIT + (nnp * 2 + 0) * 32 + vColB);
                ldm_x4_t(v1f[0], v1f[1], v1f[2], v1f[3],
                         stV + (j * 16 + vRow) * FPIT + (nnp * 2 + 1) * 32 + vColB);
                mma16816(acc_o[nnp * 4 + 0], ph[j], v0f[0], v0f[1]);
                mma16816(acc_o[nnp * 4 + 1], ph[j], v0f[2], v0f[3]);
                mma16816(acc_o[nnp * 4 + 2], ph[j], v1f[0], v1f[1]);
                mma16816(acc_o[nnp * 4 + 3], ph[j], v1f[2], v1f[3]);
            }
        }

        __syncthreads();
        if (t + 2 < 16) loadKV(t + 2, s);
        CP_COMMIT();
    }

    float i0 = 1.f / l0, i1 = 1.f / l1;
    __half* Op = Og + ((size_t)b * Sx + q0 + wid * 16) * Dx + h * HDx;
    #pragma unroll
    for (int nt = 0; nt < 8; nt++) {
        int col = nt * 8 + 2 * cq;
        *(uint32_t*)&Op[(size_t)r * Dx + col] =
            h2u(acc_o[nt][0] * i0, acc_o[nt][1] * i0);
        *(uint32_t*)&Op[(size_t)(r + 8) * Dx + col] =
            h2u(acc_o[nt][2] * i1, acc_o[nt][3] * i1);
    }
}

// ---------------- fused fp32->fp16 conversions + mask bit-packing -----------
#define CVT_N0 (Mx*Dx)
#define CVT_N1 (Dx*Dx)
#define CVT_N5 (Dx*FCx)
#define CVT_TOT (CVT_N0 + 4*CVT_N1 + 2*CVT_N5)   // 10,223,616
#define CVT_BLOCKS (CVT_TOT / 4 / 256)           // 9984
#define PK_BLOCKS (Mx / 8)                       // 512

__global__ __launch_bounds__(256)
void conv_pack(const float* __restrict__ x,
               const float* __restrict__ WQ, const float* __restrict__ WK,
               const float* __restrict__ WV, const float* __restrict__ Wfc,
               const float* __restrict__ W1, const float* __restrict__ W2,
               const int* __restrict__ mask,
               __half* __restrict__ xh, __half* __restrict__ Wqkv,
               __half* __restrict__ Wfch, __half* __restrict__ W1h,
               __half* __restrict__ W2h, uint32_t* __restrict__ mpk)
{
    if (blockIdx.x >= CVT_BLOCKS) {
        int warp = (blockIdx.x - CVT_BLOCKS) * 8 + (threadIdx.x >> 5);
        int lane = threadIdx.x & 31;
        const int* rowp = mask + (size_t)warp * 1024;
        uint32_t*  outp = mpk  + (size_t)warp * 32;
        #pragma unroll
        for (int w = 0; w < 32; w++) {
            int v = rowp[w * 32 + lane];
            uint32_t word = __ballot_sync(0xffffffffu, v != 0);
            if (lane == 0) outp[w] = word;
        }
        return;
    }

    long long q = ((long long)blockIdx.x * 256 + threadIdx.x) * 4;
    const float* src;
    __half* dst;
    long long B = CVT_N0;
    if (q < B) {
        src = x + q; dst = xh + q;
    } else if (q < B + CVT_N1) {
        long long i = q - B; int row = (int)(i / Dx), col = (int)(i % Dx);
        src = WQ + i; dst = Wqkv + (size_t)row * 3 * Dx + col;
    } else if (q < B + 2*CVT_N1) {
        long long i = q - B - CVT_N1; int row = (int)(i / Dx), col = (int)(i % Dx);
        src = WK + i; dst = Wqkv + (size_t)row * 3 * Dx + Dx + col;
    } else if (q < B + 3*CVT_N1) {
        long long i = q - B - 2*CVT_N1; int row = (int)(i / Dx), col = (int)(i % Dx);
        src = WV + i; dst = Wqkv + (size_t)row * 3 * Dx + 2 * Dx + col;
    } else if (q < B + 4*CVT_N1) {
        long long i = q - B - 3*CVT_N1;
        src = Wfc + i; dst = Wfch + i;
    } else if (q < B + 4*CVT_N1 + CVT_N5) {
        long long i = q - B - 4*CVT_N1;
        src = W1 + i; dst = W1h + i;
    } else {
        long long i = q - B - 4*CVT_N1 - CVT_N5;
        src = W2 + i; dst = W2h + i;
    }
    float4 v = *(const float4*)src;
    *(uint32_t*)dst       = h2u(v.x, v.y);
    *(uint32_t*)(dst + 2) = h2u(v.z, v.w);
}

// ---------------- split-K reduce + residual + bias + LayerNorm --------------
template<int P, bool WH, bool BIAS>
__global__ __launch_bounds__(192)
void ln_kernel(const float* __restrict__ a, const float* __restrict__ r,
               const float* __restrict__ bias,
               const float* __restrict__ g, const float* __restrict__ be,
               float* __restrict__ out, __half* __restrict__ outh)
{
    const int tid = threadIdx.x;
    const size_t base = (size_t)blockIdx.x * Dx + tid * 4;

    float x0, x1, x2, x3;
    {
        float4 xr = *(const float4*)&r[base];
        x0 = xr.x; x1 = xr.y; x2 = xr.z; x3 = xr.w;
    }
    #pragma unroll
    for (int p = 0; p < P; p++) {
        float4 xa = *(const float4*)&a[(size_t)p * Mx * Dx + base];
        x0 += xa.x; x1 += xa.y; x2 += xa.z; x3 += xa.w;
    }
    if (BIAS) {
        float4 bv = *(const float4*)&bias[tid * 4];
        x0 += bv.x; x1 += bv.y; x2 += bv.z; x3 += bv.w;
    }

    float s = x0 + x1 + x2 + x3;
    float q = x0*x0 + x1*x1 + x2*x2 + x3*x3;
    #pragma unroll
    for (int o = 16; o; o >>= 1) {
        s += __shfl_xor_sync(0xffffffffu, s, o);
        q += __shfl_xor_sync(0xffffffffu, q, o);
    }
    __shared__ float ss[6], qq[6];
    if ((tid & 31) == 0) { ss[tid >> 5] = s; qq[tid >> 5] = q; }
    __syncthreads();
    if (tid == 0) {
        float S = 0.f, Qq = 0.f;
        #pragma unroll
        for (int w = 0; w < 6; w++) { S += ss[w]; Qq += qq[w]; }
        float mean = S * (1.f / Dx);
        float var  = Qq * (1.f / Dx) - mean * mean;
        ss[0] = mean;
        qq[0] = rsqrtf(var + EPSx);
    }
    __syncthreads();
    float mean = ss[0], rstd = qq[0];

    float4 gv = *(const float4*)&g[tid * 4];
    float4 bv = *(const float4*)&be[tid * 4];
    float4 o4;
    o4.x = (x0 - mean) * rstd * gv.x + bv.x;
    o4.y = (x1 - mean) * rstd * gv.y + bv.y;
    o4.z = (x2 - mean) * rstd * gv.z + bv.z;
    o4.w = (x3 - mean) * rstd * gv.w + bv.w;
    *(float4*)&out[base] = o4;
    if (WH) {
        *(uint32_t*)&outh[base]     = h2u(o4.x, o4.y);
        *(uint32_t*)&outh[base + 2] = h2u(o4.z, o4.w);
    }
}

// ---------------- launch ----------------------------------------------------
extern "C" void kernel_launch(void* const* d_in, const int* in_sizes, int n_in,
                              void* d_out, int out_size)
{
    const float* x    = (const float*)d_in[0];
    const int*   mask = (const int*)  d_in[1];
    const float* WQ   = (const float*)d_in[2];
    const float* WK   = (const float*)d_in[3];
    const float* WV   = (const float*)d_in[4];
    const float* Wfc  = (const float*)d_in[5];
    const float* W1   = (const float*)d_in[6];
    const float* b1   = (const float*)d_in[7];
    const float* W2   = (const float*)d_in[8];
    const float* b2   = (const float*)d_in[9];
    const float* g1   = (const float*)d_in[10];
    const float* be1  = (const float*)d_in[11];
    const float* g2   = (const float*)d_in[12];
    const float* be2  = (const float*)d_in[13];
    float* out = (float*)d_out;

    __half *xh, *QKVh, *atth, *nah, *lin1h;
    __half *Wqkv, *Wfch, *W1h, *W2h;
    float *proj2, *na, *lin2p;
    uint32_t* mpk;
    cudaGetSymbolAddress((void**)&xh,     g_xh);
    cudaGetSymbolAddress((void**)&QKVh,   g_QKVh);
    cudaGetSymbolAddress((void**)&mpk,    g_mpk);
    cudaGetSymbolAddress((void**)&atth,   g_atth);
    cudaGetSymbolAddress((void**)&proj2,  g_proj2);
    cudaGetSymbolAddress((void**)&na,     g_na);
    cudaGetSymbolAddress((void**)&nah,    g_nah);
    cudaGetSymbolAddress((void**)&lin1h,  g_lin1h);
    cudaGetSymbolAddress((void**)&lin2p,  g_lin2p);
    cudaGetSymbolAddress((void**)&Wqkv,   g_Wqkv);
    cudaGetSymbolAddress((void**)&Wfch,   g_Wfch);
    cudaGetSymbolAddress((void**)&W1h,    g_W1h);
    cudaGetSymbolAddress((void**)&W2h,    g_W2h);

    constexpr int SM128 = STAGES * (128 * PITCHA + 64 * PITCHB);   // 107520
    cudaFuncSetAttribute((void*)hgemm<128,3>, cudaFuncAttributeMaxDynamicSharedMemorySize, SM128);
    cudaFuncSetAttribute((void*)hgemm<128,7>, cudaFuncAttributeMaxDynamicSharedMemorySize, SM128);
    cudaFuncSetAttribute((void*)hgemm<128,8>, cudaFuncAttributeMaxDynamicSharedMemorySize, SM128);
    cudaFuncSetAttribute(flash_kernel, cudaFuncAttributeMaxDynamicSharedMemorySize, FSMEM);

    // fused conversions + mask packing
    conv_pack<<<CVT_BLOCKS + PK_BLOCKS, 256>>>(x, WQ, WK, WV, Wfc, W1, W2, mask,
                                               xh, Wqkv, Wfch, W1h, W2h, mpk);

    // fused QKV projection (M=4096, N=2304, K=768)
    hgemm<128,7><<<dim3(3*Dx/128, Mx/128), 256, SM128>>>(xh, Wqkv, nullptr, QKVh,
                                                         Dx, Dx, 3*Dx, Dx);

    // fused attention
    __half* Qh = QKVh;
    __half* Kh = QKVh + (size_t)Mx * Dx;
    __half* Vh = QKVh + (size_t)2 * Mx * Dx;
    flash_kernel<<<dim3(Sx/128, Bx*Hx), 256, FSMEM>>>(Qh, Kh, Vh, mpk, atth);

    // output projection: split-K=3 (576 CTAs, 4 chunks each), reduce in LN1
    hgemm<128,8><<<dim3(Dx/128, Mx/128, 3), 256, SM128>>>(atth, Wfch, nullptr, proj2,
                                                          Dx/3, Dx, Dx, Dx);
    ln_kernel<3,true,false><<<Mx, 192>>>(proj2, x, nullptr, g1, be1, na, nah);

    // FC1 (768 CTAs, full K)
    hgemm<128,3><<<dim3(FCx/128, Mx/128), 256, SM128>>>(nah, W1h, b1, lin1h,
                                                        Dx, Dx, FCx, FCx);
    // FC2: split-K=3 (576 CTAs, 16 chunks each), reduce + bias in LN2
    hgemm<128,8><<<dim3(Dx/128, Mx/128, 3), 256, SM128>>>(lin1h, W2h, nullptr, lin2p,
                                                          FCx/3, FCx, Dx, Dx);
    ln_kernel<3,false,true><<<Mx, 192>>>(lin2p, na, b2, g2, be2, out, nullptr);
}